// round 17
// baseline (speedup 1.0000x reference)
#include <cuda_runtime.h>
#include <stdint.h>
#include <math.h>

#define Bx 8
#define Cx 4
#define Hx 384
#define Wx 384
#define SLICE (Hx*Wx)          // 147456
#define NSLICE (Bx*Cx)         // 32
#define BIGI 768               // = H + W, finite sentinel (matches reference)
#define INFP 0x3FFF3FFFu       // packed u16x2 "infinity" (saturating math keeps it big)
#define ONEP 0x00010001u
#define PADSQ 0xFE01FE01u      // packed 255^2 halves: pad candidates always lose (>16)
#define ROWS 4                 // rows per k_row band
#define XT 128                 // columns per k_row block (third of a row)
#define XW (XT + 8)            // staged window incl. +-4 pad = 136 (mult of 4)

// Scratch (no cudaMalloc allowed).
__device__ unsigned long long g_pack[Bx*SLICE]; // [b][h][w] -> g for 4 classes, u16x4 (9 MB)
__device__ unsigned int   g_dmax_bits[NSLICE];
__device__ double         g_S[NSLICE];          // sum of p_c over target pixels
__device__ double         g_acc;                // sum of p_c * dt over non-target pixels
__device__ unsigned int   g_count;              // zero-init; reset by last k_row block

__device__ __forceinline__ float sqrt_approx(float x) {
    float r;
    asm("sqrt.approx.f32 %0, %1;" : "=f"(r) : "f"(x));
    return r;
}

// ---------------------------------------------------------------------------
// Phase 1: vertical 1D distance per (b,w) column for ALL 4 classes packed
// u16x4. One warp per column; lane owns a 12-pixel h-segment. Exact segmented
// min-plus scan; unclamped math + final clamp(768) == reference's per-step
// clamp since increments are +1. Labels staged through shared (coalesced).
__global__ void __launch_bounds__(256) k_phase1(const int* __restrict__ targets) {
    __shared__ unsigned long long sg[Hx][9];   // 27 KB staging (pad vs bank conflicts)
    __shared__ unsigned char s_t[Hx * 8];      // 3 KB label tile [h][w-w0]

    int tid = threadIdx.x, wid = tid >> 5, lane = tid & 31;
    if (blockIdx.x == 0 && tid < NSLICE) {     // fused init
        g_dmax_bits[tid] = 0u; g_S[tid] = 0.0;
        if (tid == 0) g_acc = 0.0;
    }

    int b  = blockIdx.x / (Wx / 8);
    int w0 = (blockIdx.x % (Wx / 8)) * 8;

    {
        const int4* tp4 = (const int4*)(targets + (size_t)b * SLICE + w0);
        #pragma unroll
        for (int q = tid; q < Hx * 2; q += 256) {
            int h = q >> 1, hf = q & 1;
            int4 v = __ldg(&tp4[h * (Wx / 4) + hf]);
            int base = h * 8 + hf * 4;
            s_t[base + 0] = (unsigned char)v.x;
            s_t[base + 1] = (unsigned char)v.y;
            s_t[base + 2] = (unsigned char)v.z;
            s_t[base + 3] = (unsigned char)v.w;
        }
    }
    __syncthreads();

    int h0 = lane * 12;
    uint32_t mlo[12], mhi[12];
    #pragma unroll
    for (int i = 0; i < 12; ++i) {
        int t = s_t[(h0 + i) * 8 + wid];
        mlo[i] = (t == 0) ? 0xFFFF0000u : (t == 1) ? 0x0000FFFFu : 0xFFFFFFFFu;
        mhi[i] = (t == 2) ? 0xFFFF0000u : (t == 3) ? 0x0000FFFFu : 0xFFFFFFFFu;
    }

    uint32_t flo = INFP, fhi = INFP;
    #pragma unroll
    for (int i = 0; i < 12; ++i) { flo = __vaddus2(flo, ONEP) & mlo[i]; fhi = __vaddus2(fhi, ONEP) & mhi[i]; }
    uint32_t blo = INFP, bhi = INFP;
    #pragma unroll
    for (int i = 11; i >= 0; --i) { blo = __vaddus2(blo, ONEP) & mlo[i]; bhi = __vaddus2(bhi, ONEP) & mhi[i]; }

    uint32_t filo = flo, fihi = fhi, bilo = blo, bihi = bhi;
    #pragma unroll
    for (int d = 1; d < 32; d <<= 1) {
        uint32_t k = ((12u * d) << 16) | (12u * d);
        uint32_t a0 = __shfl_up_sync(0xffffffffu, filo, d);
        uint32_t a1 = __shfl_up_sync(0xffffffffu, fihi, d);
        if (lane >= d) { filo = __vminu2(filo, __vaddus2(a0, k)); fihi = __vminu2(fihi, __vaddus2(a1, k)); }
        uint32_t c0 = __shfl_down_sync(0xffffffffu, bilo, d);
        uint32_t c1 = __shfl_down_sync(0xffffffffu, bihi, d);
        if (lane < 32 - d) { bilo = __vminu2(bilo, __vaddus2(c0, k)); bihi = __vminu2(bihi, __vaddus2(c1, k)); }
    }
    uint32_t cflo = __shfl_up_sync(0xffffffffu, filo, 1);
    uint32_t cfhi = __shfl_up_sync(0xffffffffu, fihi, 1);
    if (lane == 0) { cflo = INFP; cfhi = INFP; }
    uint32_t cblo = __shfl_down_sync(0xffffffffu, bilo, 1);
    uint32_t cbhi = __shfl_down_sync(0xffffffffu, bihi, 1);
    if (lane == 31) { cblo = INFP; cbhi = INFP; }

    unsigned long long Df[12];
    uint32_t rlo = cflo, rhi = cfhi;
    flo = INFP; fhi = INFP;
    #pragma unroll
    for (int i = 0; i < 12; ++i) {
        rlo = __vaddus2(rlo, ONEP); rhi = __vaddus2(rhi, ONEP);
        flo = __vaddus2(flo, ONEP) & mlo[i]; fhi = __vaddus2(fhi, ONEP) & mhi[i];
        uint32_t xlo = __vminu2(flo, rlo), xhi = __vminu2(fhi, rhi);
        Df[i] = ((unsigned long long)xhi << 32) | xlo;
    }
    const uint32_t CLP = ((uint32_t)BIGI << 16) | (uint32_t)BIGI;
    rlo = cblo; rhi = cbhi; blo = INFP; bhi = INFP;
    #pragma unroll
    for (int i = 11; i >= 0; --i) {
        rlo = __vaddus2(rlo, ONEP); rhi = __vaddus2(rhi, ONEP);
        blo = __vaddus2(blo, ONEP) & mlo[i]; bhi = __vaddus2(bhi, ONEP) & mhi[i];
        uint32_t xlo = __vminu2(blo, rlo), xhi = __vminu2(bhi, rhi);
        xlo = __vminu2(__vminu2(xlo, (uint32_t)Df[i]), CLP);
        xhi = __vminu2(__vminu2(xhi, (uint32_t)(Df[i] >> 32)), CLP);
        sg[h0 + i][wid] = ((unsigned long long)xhi << 32) | xlo;
    }
    __syncthreads();

    unsigned long long* gp = g_pack + (size_t)b * SLICE;
    #pragma unroll
    for (int e = tid; e < Hx * 8; e += 256) {
        int h = e >> 3, wl = e & 7;
        gp[(size_t)h * Wx + w0 + wl] = sg[h][wl];
    }
}

// ---------------------------------------------------------------------------
// Rare exact tail for m > 16: full pruned scan from global packed g.
__device__ __noinline__ int tail_m(const unsigned long long* gr, int y, int sh) {
    int v0 = (int)((gr[y] >> sh) & 0xFFFF);
    int m = v0 * v0;
    for (int r = 1; r < Wx && r * r < m; ++r) {
        int jl = y - r, jr = y + r;
        if (jl >= 0) { int v = (int)((gr[jl] >> sh) & 0xFFFF); m = min(m, v * v + r * r); }
        if (jr < Wx) { int v = (int)((gr[jr] >> sh) & 0xFFFF); m = min(m, v * v + r * r); }
    }
    return m;
}

// ---------------------------------------------------------------------------
// One pixel, fully register-explicit. Window args are named uint32 components;
// logits are named float components.
#define PIX(a3m,a2m,a1m,a0_,a1p,a2p,a3p, c3m,c2m,c1m,c0_,c1p,c2p,c3p, lx0,lx1,lx2,lx3, tx, yy) do { \
    uint32_t m01 = (a0_), m23 = (c0_);                                        \
    m01 = __vminu2(m01, __vaddus2((a1m), K1));                                \
    m01 = __vminu2(m01, __vaddus2((a1p), K1));                                \
    m01 = __vminu2(m01, __vaddus2((a2m), K2));                                \
    m01 = __vminu2(m01, __vaddus2((a2p), K2));                                \
    m01 = __vminu2(m01, __vaddus2((a3m), K3));                                \
    m01 = __vminu2(m01, __vaddus2((a3p), K3));                                \
    m23 = __vminu2(m23, __vaddus2((c1m), K1));                                \
    m23 = __vminu2(m23, __vaddus2((c1p), K1));                                \
    m23 = __vminu2(m23, __vaddus2((c2m), K2));                                \
    m23 = __vminu2(m23, __vaddus2((c2p), K2));                                \
    m23 = __vminu2(m23, __vaddus2((c3m), K3));                                \
    m23 = __vminu2(m23, __vaddus2((c3p), K3));                                \
    int m0 = (int)(m01 & 0xFFFFu), m1 = (int)(m01 >> 16);                     \
    int m2 = (int)(m23 & 0xFFFFu), m3 = (int)(m23 >> 16);                     \
    if (__builtin_expect(max(max(m0, m1), max(m2, m3)) > 16, 0)) {            \
        if (m0 > 16) m0 = tail_m(gr, (yy), 0);                                \
        if (m1 > 16) m1 = tail_m(gr, (yy), 16);                               \
        if (m2 > 16) m2 = tail_m(gr, (yy), 32);                               \
        if (m3 > 16) m3 = tail_m(gr, (yy), 48);                               \
    }                                                                         \
    float d0 = sqrt_approx((float)m0);                                        \
    float d1 = sqrt_approx((float)m1);                                        \
    float d2 = sqrt_approx((float)m2);                                        \
    float d3 = sqrt_approx((float)m3);                                        \
    float e0 = __expf((lx0) - (lx3));                                         \
    float e1 = __expf((lx1) - (lx3));                                         \
    float e2 = __expf((lx2) - (lx3));                                         \
    float inv = __fdividef(1.0f, e0 + e1 + e2 + 1.0f);                        \
    acc += (e0 * d0 + e1 * d1 + e2 * d2 + d3) * inv;                          \
    Sv0 += ((tx) == 0) ? e0 * inv : 0.0f;                                     \
    Sv1 += ((tx) == 1) ? e1 * inv : 0.0f;                                     \
    Sv2 += ((tx) == 2) ? e2 * inv : 0.0f;                                     \
    Sv3 += ((tx) == 3) ? inv      : 0.0f;                                     \
    Mm0 = max(Mm0, m0); Mm1 = max(Mm1, m1);                                   \
    Mm2 = max(Mm2, m2); Mm3 = max(Mm3, m3);                                   \
} while (0)

// ---------------------------------------------------------------------------
// Phase 2+3 fused + finalization: one 128-thread block per (b, 4-row band,
// 128-column third). 2304 blocks -> ~62 warps/SM ceiling (was 21). One warp
// per row; each thread handles 4 consecutive pixels (float4/int4 loads, 6
// conflict-free uint4 LDS for the radius-3 windows).
//   dt_c(y) = sqrt( min_j g_c(j)^2 + (y-j)^2 )
// Fast path: min over |r|<=3 of min(g,255)^2 + r^2 via u16x2 SIMD. Exact when
// m <= 16 (every excluded candidate -- r>=4 or clamped g>=255 -- has value
// >= 16; ties at 16 leave the min unchanged); else rare exact tail (~0.03%).
// Boundary pads PADSQ outside the image; interior third-boundaries stage real
// g values -> bit-identical results. Softmax shifted by l3 (shift-invariant).
// Last block (counter) finalizes:
//   loss = ( sum p_c*dt_c - sum_s dmax_s*S_s ) / (C * B*C*H*W).
__global__ void __launch_bounds__(128) k_row(const float* __restrict__ outputs,
                                             const int*   __restrict__ targets,
                                             float*       __restrict__ out) {
    __shared__ __align__(16) uint32_t s01[ROWS][XW];   // 2.1 KB
    __shared__ __align__(16) uint32_t s23[ROWS][XW];
    __shared__ float s_red[4][9];
    __shared__ int s_last;

    int tid = threadIdx.x;
    int blk = blockIdx.x;                  // 0 .. Bx*(Hx/ROWS)*3 - 1
    int x0  = (blk % 3) * XT;
    int band = blk / 3;
    int b    = band / (Hx / ROWS);
    int h0   = (band % (Hx / ROWS)) * ROWS;

    const unsigned long long* gband = g_pack + (size_t)b * SLICE + (size_t)h0 * Wx;

    // stage clamped-square packed window [x0-4, x0+XT+4) for the 4 rows
    for (int i = tid; i < ROWS * XW; i += 128) {
        int r = i / XW, k = i - r * XW;
        int x = x0 - 4 + k;
        uint32_t p01 = PADSQ, p23 = PADSQ;
        if ((unsigned)x < (unsigned)Wx) {
            unsigned long long v = gband[(size_t)r * Wx + x];
            int v0 = min((int)(v & 0xFFFF), 255);
            int v1 = min((int)((v >> 16) & 0xFFFF), 255);
            int v2 = min((int)((v >> 32) & 0xFFFF), 255);
            int v3 = min((int)((v >> 48) & 0xFFFF), 255);
            p01 = (uint32_t)(v0 * v0) | ((uint32_t)(v1 * v1) << 16);
            p23 = (uint32_t)(v2 * v2) | ((uint32_t)(v3 * v3) << 16);
        }
        s01[r][k] = p01;
        s23[r][k] = p23;
    }
    __syncthreads();

    int rw = tid >> 5;                     // one warp per row
    int y0 = (tid & 31) * 4;               // local pixel group, 0..124

    const float* ob = outputs + (size_t)b * Cx * SLICE + (size_t)(h0 + rw) * Wx + x0 + y0;
    float4 L0 = *(const float4*)(ob);
    float4 L1 = *(const float4*)(ob + SLICE);
    float4 L2 = *(const float4*)(ob + 2 * SLICE);
    float4 L3 = *(const float4*)(ob + 3 * SLICE);
    int4   T4 = *(const int4*)(targets + (size_t)b * SLICE + (size_t)(h0 + rw) * Wx + x0 + y0);

    // windows: logical x0-4+y0 .. +11 (16B-aligned, conflict-free)
    const uint4* A4 = (const uint4*)&s01[rw][y0];
    const uint4* C4 = (const uint4*)&s23[rw][y0];
    uint4 Aa = A4[0], Ab = A4[1], Ac = A4[2];
    uint4 Ca = C4[0], Cb = C4[1], Cc = C4[2];

    const unsigned long long* gr = gband + (size_t)rw * Wx;
    const uint32_t K1 = 0x00010001u, K2 = 0x00040004u, K3 = 0x00090009u;

    float acc = 0.0f;
    float Sv0 = 0.0f, Sv1 = 0.0f, Sv2 = 0.0f, Sv3 = 0.0f;
    int   Mm0 = 0, Mm1 = 0, Mm2 = 0, Mm3 = 0;
    int yg = x0 + y0;

    PIX(Aa.y, Aa.z, Aa.w, Ab.x, Ab.y, Ab.z, Ab.w,
        Ca.y, Ca.z, Ca.w, Cb.x, Cb.y, Cb.z, Cb.w,
        L0.x, L1.x, L2.x, L3.x, T4.x, yg + 0);
    PIX(Aa.z, Aa.w, Ab.x, Ab.y, Ab.z, Ab.w, Ac.x,
        Ca.z, Ca.w, Cb.x, Cb.y, Cb.z, Cb.w, Cc.x,
        L0.y, L1.y, L2.y, L3.y, T4.y, yg + 1);
    PIX(Aa.w, Ab.x, Ab.y, Ab.z, Ab.w, Ac.x, Ac.y,
        Ca.w, Cb.x, Cb.y, Cb.z, Cb.w, Cc.x, Cc.y,
        L0.z, L1.z, L2.z, L3.z, T4.z, yg + 2);
    PIX(Ab.x, Ab.y, Ab.z, Ab.w, Ac.x, Ac.y, Ac.z,
        Cb.x, Cb.y, Cb.z, Cb.w, Cc.x, Cc.y, Cc.z,
        L0.w, L1.w, L2.w, L3.w, T4.w, yg + 3);

    // block reduction (sqrt is monotone -> reduce m as int, sqrt once)
    float Lm0 = sqrt_approx((float)Mm0);
    float Lm1 = sqrt_approx((float)Mm1);
    float Lm2 = sqrt_approx((float)Mm2);
    float Lm3 = sqrt_approx((float)Mm3);
    #pragma unroll
    for (int off = 16; off > 0; off >>= 1) {
        acc += __shfl_down_sync(0xffffffffu, acc, off);
        Sv0 += __shfl_down_sync(0xffffffffu, Sv0, off);
        Sv1 += __shfl_down_sync(0xffffffffu, Sv1, off);
        Sv2 += __shfl_down_sync(0xffffffffu, Sv2, off);
        Sv3 += __shfl_down_sync(0xffffffffu, Sv3, off);
        Lm0  = fmaxf(Lm0, __shfl_down_sync(0xffffffffu, Lm0, off));
        Lm1  = fmaxf(Lm1, __shfl_down_sync(0xffffffffu, Lm1, off));
        Lm2  = fmaxf(Lm2, __shfl_down_sync(0xffffffffu, Lm2, off));
        Lm3  = fmaxf(Lm3, __shfl_down_sync(0xffffffffu, Lm3, off));
    }
    if ((tid & 31) == 0) {
        s_red[rw][0] = acc;
        s_red[rw][1] = Sv0; s_red[rw][2] = Sv1; s_red[rw][3] = Sv2; s_red[rw][4] = Sv3;
        s_red[rw][5] = Lm0; s_red[rw][6] = Lm1; s_red[rw][7] = Lm2; s_red[rw][8] = Lm3;
    }
    __syncthreads();
    if (tid < Cx) {                         // threads 0..3: one class each
        int cc = tid;
        float s = s_red[0][1 + cc] + s_red[1][1 + cc] + s_red[2][1 + cc] + s_red[3][1 + cc];
        float m = fmaxf(fmaxf(s_red[0][5 + cc], s_red[1][5 + cc]),
                        fmaxf(s_red[2][5 + cc], s_red[3][5 + cc]));
        atomicAdd(&g_S[b * Cx + cc], (double)s);
        atomicMax(&g_dmax_bits[b * Cx + cc], __float_as_uint(m));
        if (cc == 0) {
            double aa = (double)s_red[0][0] + s_red[1][0] + s_red[2][0] + s_red[3][0];
            atomicAdd(&g_acc, aa);
        }
        __threadfence();                    // release this block's contributions
    }
    __syncthreads();
    if (tid == 0)
        s_last = (atomicAdd(&g_count, 1u) == (unsigned)(gridDim.x - 1));
    __syncthreads();

    if (s_last && tid < 32) {
        __threadfence();                    // acquire all blocks' contributions
        double v = (double)__uint_as_float(((volatile unsigned int*)g_dmax_bits)[tid])
                 * ((volatile double*)g_S)[tid];
        #pragma unroll
        for (int off = 16; off > 0; off >>= 1)
            v += __shfl_down_sync(0xffffffffu, v, off);
        if (tid == 0) {
            double aa = *((volatile double*)&g_acc);
            out[0] = (float)((aa - v) / ((double)Cx * (double)Bx * Cx * Hx * Wx));
            g_count = 0u;                   // reset for next (graph) replay
        }
    }
}

// ---------------------------------------------------------------------------
extern "C" void kernel_launch(void* const* d_in, const int* in_sizes, int n_in,
                              void* d_out, int out_size) {
    const float* outputs = (const float*)d_in[0];
    const int*   targets = (const int*)d_in[1];
    float*       out     = (float*)d_out;

    k_phase1<<<Bx * (Wx / 8), 256>>>(targets);
    k_row<<<Bx * (Hx / ROWS) * 3, 128>>>(outputs, targets, out);
}